// round 12
// baseline (speedup 1.0000x reference)
#include <cuda_runtime.h>
#include <cuda_fp16.h>
#include <cstdint>

#define BB   256
#define TT   256
#define KTOK 128
#define HH   512
#define G4H  2048
#define DD   128

#define NCTA 256
#define NTHR 128

#define BG_PITCH 80u                    // 32 gate cols * 2B + 16B pad
#define BO_PITCH 16u                    // 8 cols (2 real + 6 pad) * 2B
#define BO_BUF   8192u

#define BG_OFF  0u
#define BO_OFF  40960u                  // 2 buffers x 8192
#define XG_OFF  57344u
#define SMEM_BYTES 57472u

__device__ __half    g_h[2][BB * HH];
__device__ unsigned  g_cnt[4 * 16 * 64];   // [domain][block] producer counters, 256B apart

__global__ void reset_kernel() {
    for (int i = threadIdx.x; i < 4 * 16 * 64; i += blockDim.x) g_cnt[i] = 0u;
}

__device__ __forceinline__ uint32_t smem_u32(const void* p) {
    uint32_t a;
    asm("{ .reg .u64 t; cvta.to.shared.u64 t, %1; cvt.u32.u64 %0, t; }" : "=r"(a) : "l"(p));
    return a;
}
__device__ __forceinline__ float tanha(float x) {
    float r; asm("tanh.approx.f32 %0, %1;" : "=f"(r) : "f"(x)); return r;
}
__device__ __forceinline__ float sigm(float x) { return fmaf(0.5f, tanha(0.5f * x), 0.5f); }

__device__ __forceinline__ void ldsm_x4t(uint32_t* r, uint32_t addr) {
    asm volatile("ldmatrix.sync.aligned.m8n8.x4.trans.shared.b16 {%0,%1,%2,%3}, [%4];"
        : "=r"(r[0]), "=r"(r[1]), "=r"(r[2]), "=r"(r[3]) : "r"(addr));
}
__device__ __forceinline__ void ldsm_x2t(uint32_t* r, uint32_t addr) {
    asm volatile("ldmatrix.sync.aligned.m8n8.x2.trans.shared.b16 {%0,%1}, [%2];"
        : "=r"(r[0]), "=r"(r[1]) : "r"(addr));
}
__device__ __forceinline__ void mma16816(float* d, uint32_t a0, uint32_t a1, uint32_t a2,
                                         uint32_t a3, const uint32_t* b) {
    asm volatile("mma.sync.aligned.m16n8k16.row.col.f32.f16.f16.f32 "
        "{%0,%1,%2,%3}, {%4,%5,%6,%7}, {%8,%9}, {%0,%1,%2,%3};"
        : "+f"(d[0]), "+f"(d[1]), "+f"(d[2]), "+f"(d[3])
        : "r"(a0), "r"(a1), "r"(a2), "r"(a3), "r"(b[0]), "r"(b[1]));
}

// k permutation within 32-blocks (R6, proven): direct LDG.128 -> mma A fragments
__device__ __forceinline__ int vk_to_ak(int vk) {
    int kfl = (vk >> 4) & 1, pair = (vk >> 3) & 1, qc = (vk >> 1) & 3, elem = vk & 1;
    return (vk & ~31) + 8 * qc + kfl * 4 + pair * 2 + elem;
}
__device__ __forceinline__ int ak_to_vk(int ak) {
    int qc = (ak >> 3) & 3, j = ak & 7;
    return (ak & ~31) + (j >> 2) * 16 + ((j >> 1) & 1) * 8 + qc * 2 + (j & 1);
}

__global__ void __launch_bounds__(NTHR, 2) lstm_mma_kernel(
    const float* __restrict__ z,     const float* __restrict__ Wz,
    const float* __restrict__ bz,    const float* __restrict__ token,
    const float* __restrict__ Wi,    const float* __restrict__ Wh,
    const float* __restrict__ bh,    const float* __restrict__ Wout,
    const float* __restrict__ bout,  float* __restrict__ out)
{
    extern __shared__ char smem[];
    const uint32_t sb = smem_u32(smem);

    const int tid  = threadIdx.x;
    const int lane = tid & 31;
    const int w    = tid >> 5;            // warp 0..3 (m-tile within quarter)
    const int mqd  = blockIdx.x >> 6;     // batch quarter = sync domain (0..3)
    const int jg   = blockIdx.x & 63;     // unit group 0..63 (8 units)
    const int m0   = mqd * 64;
    const int j0   = jg * 8;
    const int Bown = jg >> 2;             // k-block this CTA produces (0..15)

    const int qr   = lane >> 2;
    const int qc   = lane & 3;
    const int row0 = w * 16 + qr;         // 0..63 within quarter
    const int u0   = qc * 2;

    const uint32_t bgLane = sb + BG_OFF + (uint32_t)(lane & 15) * BG_PITCH
                          + (uint32_t)(lane >> 4) * 16u;
    const uint32_t boLane = sb + BO_OFF + (uint32_t)(lane & 15) * BO_PITCH;

    float* sxg = (float*)(smem + XG_OFF);
    unsigned* dom = &g_cnt[mqd * 16 * 64];
    unsigned* ownFlag = &dom[Bown * 64];

    // lane l polls block (Bown+1+l)&15
    const int pollBlk = (Bown + 1 + (lane & 15)) & 15;
    unsigned* pollAddr = &dom[pollBlk * 64];

    // ---------------- one-time init ----------------
    for (int i = tid; i < 1024; i += NTHR) ((uint4*)(smem + BO_OFF))[i] = make_uint4(0, 0, 0, 0);

    // Wh slice -> fp16 smem, VIRTUAL k order
    for (int idx = tid; idx < 512 * 32; idx += NTHR) {
        int vk = idx >> 5, n = idx & 31;
        int ak = vk_to_ak(vk);
        float v = __ldg(&Wh[(size_t)ak * G4H + (n >> 3) * HH + j0 + (n & 7)]);
        *(__half*)(smem + BG_OFF + (uint32_t)vk * BG_PITCH + (uint32_t)n * 2u) = __float2half_rn(v);
    }
    if (tid < 32) {
        int col = (tid >> 3) * HH + j0 + (tid & 7);
        float s = bh[col];
        #pragma unroll 4
        for (int k = 0; k < KTOK; ++k)
            s = fmaf(token[k], __ldg(&Wi[(size_t)k * G4H + col]), s);
        sxg[tid] = s;
    }
    {   // h0 = relu(z @ Wz + bz): thread -> row tid>>1 (0..63), 4 units
        const int r  = tid >> 1;
        const int ub = (tid & 1) * 4;
        float a[4];
        #pragma unroll
        for (int q = 0; q < 4; ++q) a[q] = bz[j0 + ub + q];
        const float* zr = z + (size_t)(m0 + r) * KTOK;
        #pragma unroll 4
        for (int k = 0; k < KTOK; ++k) {
            float zv = __ldg(zr + k);
            float4 w4 = __ldg((const float4*)&Wz[(size_t)k * HH + j0 + ub]);
            a[0] = fmaf(zv, w4.x, a[0]); a[1] = fmaf(zv, w4.y, a[1]);
            a[2] = fmaf(zv, w4.z, a[2]); a[3] = fmaf(zv, w4.w, a[3]);
        }
        __half2* hp = (__half2*)&g_h[0][(size_t)(m0 + r) * HH + j0 + ub];
        hp[0] = __floats2half2_rn(fmaxf(a[0], 0.f), fmaxf(a[1], 0.f));
        hp[1] = __floats2half2_rn(fmaxf(a[2], 0.f), fmaxf(a[3], 0.f));
    }
    __syncthreads();
    if (tid == 0) {   // publish h0
        asm volatile("membar.gl;" ::: "memory");
        asm volatile("red.global.add.u32 [%0], %1;" :: "l"(ownFlag), "r"(1u) : "memory");
    }

    float c4[4] = {0.f, 0.f, 0.f, 0.f};
    float2 wo[4];

    // ---------------- sequential loop ----------------
    #pragma unroll 1
    for (int t = 0; t <= TT; ++t) {
        const __half* hsrc = g_h[t & 1];
        const int te = t - 1;
        const unsigned target = 4u * (unsigned)(t + 1);

        const __half* aRow0 = hsrc + (size_t)(m0 + row0) * HH + 8 * qc;
        const __half* aRow8 = aRow0 + 8 * HH;
        const uint32_t boSel = boLane + (uint32_t)(t & 1) * BO_BUF;

        unsigned fval;
        asm volatile("ld.global.cg.u32 %0, [%1];" : "=r"(fval) : "l"(pollAddr));
        // wait for producer group g (blocks at lanes g*4..g*4+3); nanosleep backoff
        #define WAITGRP(g) do {                                                        \
            const unsigned _m = 0xFu << ((g) * 4);                                     \
            unsigned _b = __ballot_sync(0xffffffffu, fval >= target);                  \
            while ((_b & _m) != _m) {                                                  \
                __nanosleep(50);                                                       \
                if (lane < 16)                                                         \
                    asm volatile("ld.global.cg.u32 %0, [%1];" : "=r"(fval) : "l"(pollAddr)); \
                _b = __ballot_sync(0xffffffffu, fval >= target);                       \
            }                                                                          \
            asm volatile("membar.gl;" ::: "memory");                                   \
        } while (0)

        WAITGRP(0);

        // prologue: issue LDGs for blocks i=0..3 (rotated: b = Bown+1+i)
        uint4 ra[4], rb[4];
        #pragma unroll
        for (int p = 0; p < 4; ++p) {
            const int b = (Bown + 1 + p) & 15;
            ra[p] = __ldcg((const uint4*)(aRow0 + b * 32));
            rb[p] = __ldcg((const uint4*)(aRow8 + b * 32));
        }

        // prefetch Wout_t for next iteration (overlaps mainloop)
        if (t < TT) {
            const float* Wo = Wout + (size_t)t * HH * DD + jg * 2;
            #pragma unroll
            for (int r = 0; r < 4; ++r)
                wo[r] = __ldcg((const float2*)(Wo + (size_t)(tid * 4 + r) * DD));
        }

        float acc[5][4];
        #pragma unroll
        for (int n = 0; n < 5; ++n)
            #pragma unroll
            for (int e = 0; e < 4; ++e) acc[n][e] = 0.f;

        #pragma unroll
        for (int i = 0; i < 16; ++i) {
            if (i == 0) WAITGRP(1);
            if (i == 4) WAITGRP(2);
            if (i == 8) WAITGRP(3);
            const int slot = i & 3;
            const int b = (Bown + 1 + i) & 15;
            const uint4 va = ra[slot], vb = rb[slot];
            if (i + 4 < 16) {
                const int bn = (Bown + 1 + i + 4) & 15;
                ra[slot] = __ldcg((const uint4*)(aRow0 + bn * 32));
                rb[slot] = __ldcg((const uint4*)(aRow8 + bn * 32));
            }
            #pragma unroll
            for (int kfl = 0; kfl < 2; ++kfl) {
                const uint32_t krow = (uint32_t)(b * 32 + kfl * 16);
                uint32_t b1[4], b2[4], b3[2];
                ldsm_x4t(b1, bgLane + krow * BG_PITCH);
                ldsm_x4t(b2, bgLane + krow * BG_PITCH + 32u);
                ldsm_x2t(b3, boSel + krow * BO_PITCH);
                const uint32_t a0 = kfl ? va.z : va.x;
                const uint32_t a1 = kfl ? vb.z : vb.x;
                const uint32_t a2 = kfl ? va.w : va.y;
                const uint32_t a3 = kfl ? vb.w : vb.y;
                mma16816(acc[0], a0, a1, a2, a3, b1);
                mma16816(acc[1], a0, a1, a2, a3, b1 + 2);
                mma16816(acc[2], a0, a1, a2, a3, b2);
                mma16816(acc[3], a0, a1, a2, a3, b2 + 2);
                mma16816(acc[4], a0, a1, a2, a3, b3);
            }
        }
        #undef WAITGRP

        // ---- critical path: cell update + h store + publish ----
        if (t < TT) {
            __half* hdst = &g_h[(t + 1) & 1][0];
            float hv[4];
            #pragma unroll
            for (int e = 0; e < 4; ++e) {
                const int u = u0 + (e & 1);
                float gi = sigm (acc[0][e] + sxg[u]);
                float gf = sigm (acc[1][e] + sxg[8 + u]);
                float gg = tanha(acc[2][e] + sxg[16 + u]);
                float go = sigm (acc[3][e] + sxg[24 + u]);
                float cv = gf * c4[e] + gi * gg;
                c4[e] = cv;
                hv[e] = go * tanha(cv);
            }
            __half2 h01 = __floats2half2_rn(hv[0], hv[1]);
            __half2 h23 = __floats2half2_rn(hv[2], hv[3]);
            __stcg((__half2*)&hdst[(size_t)(m0 + row0) * HH + j0 + u0], h01);
            __stcg((__half2*)&hdst[(size_t)(m0 + row0 + 8) * HH + j0 + u0], h23);

            // BO staging for step t+1 (alternate buffer)
            const uint32_t boNext = BO_OFF + (uint32_t)((t + 1) & 1) * BO_BUF;
            #pragma unroll
            for (int r = 0; r < 4; ++r) {
                __half2 p = __floats2half2_rn(wo[r].x, wo[r].y);
                *(uint32_t*)(smem + boNext + (uint32_t)ak_to_vk(tid * 4 + r) * BO_PITCH) = *(uint32_t*)&p;
            }

            __syncthreads();
            if (tid == 0) {   // publish h_{t+1}
                asm volatile("membar.gl;" ::: "memory");
                asm volatile("red.global.add.u32 [%0], %1;" :: "l"(ownFlag), "r"(1u) : "memory");
            }
        }

        // ---- shadow: out store ----
        if (t >= 1 && qc == 0) {
            const float2 bo = *(const float2*)&bout[te * DD + jg * 2];
            float2 o0 = make_float2(acc[4][0] + bo.x, acc[4][1] + bo.y);
            float2 o1 = make_float2(acc[4][2] + bo.x, acc[4][3] + bo.y);
            *(float2*)&out[(size_t)(m0 + row0) * TT * DD + (size_t)te * DD + jg * 2] = o0;
            *(float2*)&out[(size_t)(m0 + row0 + 8) * TT * DD + (size_t)te * DD + jg * 2] = o1;
        }
    }
}

extern "C" void kernel_launch(void* const* d_in, const int* in_sizes, int n_in,
                              void* d_out, int out_size) {
    const float* z     = (const float*)d_in[0];
    const float* Wz    = (const float*)d_in[1];
    const float* bz    = (const float*)d_in[2];
    const float* token = (const float*)d_in[3];
    const float* Wi    = (const float*)d_in[4];
    const float* Wh    = (const float*)d_in[5];
    const float* bh    = (const float*)d_in[6];
    const float* Wout  = (const float*)d_in[7];
    const float* bout  = (const float*)d_in[8];
    float* out = (float*)d_out;

    cudaFuncSetAttribute(lstm_mma_kernel, cudaFuncAttributeMaxDynamicSharedMemorySize, SMEM_BYTES);
    reset_kernel<<<1, 256>>>();
    lstm_mma_kernel<<<NCTA, NTHR, SMEM_BYTES>>>(z, Wz, bz, token, Wi, Wh, bh, Wout, bout, out);
}

// round 13
// speedup vs baseline: 1.3262x; 1.3262x over previous
#include <cuda_runtime.h>
#include <cuda_fp16.h>
#include <cstdint>

#define BB   256
#define TT   256
#define KTOK 128
#define HH   512
#define G4H  2048
#define DD   128

#define NCTA 128
#define NTHR 256

#define BG_PITCH 80u                    // 32 gate cols * 2B + 16B pad
#define BO_PITCH 16u                    // 8 cols (2 real + 6 pad) * 2B
#define BO_BUF   8192u

#define BG_OFF  0u
#define BO_OFF  40960u                  // 2 buffers x 8192
#define XG_OFF  57344u
#define SMEM_BYTES 57472u

__device__ __half    g_h[2][BB * HH];
__device__ unsigned  g_cnt[2 * 32];     // per-half arrival counters

__global__ void reset_kernel() { if (threadIdx.x < 64) g_cnt[threadIdx.x] = 0u; }

__device__ __forceinline__ uint32_t smem_u32(const void* p) {
    uint32_t a;
    asm("{ .reg .u64 t; cvta.to.shared.u64 t, %1; cvt.u32.u64 %0, t; }" : "=r"(a) : "l"(p));
    return a;
}
__device__ __forceinline__ float tanha(float x) {
    float r; asm("tanh.approx.f32 %0, %1;" : "=f"(r) : "f"(x)); return r;
}
__device__ __forceinline__ float sigm(float x) { return fmaf(0.5f, tanha(0.5f * x), 0.5f); }

__device__ __forceinline__ void ldsm_x4t(uint32_t* r, uint32_t addr) {
    asm volatile("ldmatrix.sync.aligned.m8n8.x4.trans.shared.b16 {%0,%1,%2,%3}, [%4];"
        : "=r"(r[0]), "=r"(r[1]), "=r"(r[2]), "=r"(r[3]) : "r"(addr));
}
__device__ __forceinline__ void ldsm_x2t(uint32_t* r, uint32_t addr) {
    asm volatile("ldmatrix.sync.aligned.m8n8.x2.trans.shared.b16 {%0,%1}, [%2];"
        : "=r"(r[0]), "=r"(r[1]) : "r"(addr));
}
__device__ __forceinline__ void mma16816(float* d, uint32_t a0, uint32_t a1, uint32_t a2,
                                         uint32_t a3, const uint32_t* b) {
    asm volatile("mma.sync.aligned.m16n8k16.row.col.f32.f16.f16.f32 "
        "{%0,%1,%2,%3}, {%4,%5,%6,%7}, {%8,%9}, {%0,%1,%2,%3};"
        : "+f"(d[0]), "+f"(d[1]), "+f"(d[2]), "+f"(d[3])
        : "r"(a0), "r"(a1), "r"(a2), "r"(a3), "r"(b[0]), "r"(b[1]));
}

// k permutation within 32-blocks (R6, proven): direct LDG.128 -> mma A fragments
__device__ __forceinline__ int vk_to_ak(int vk) {
    int kfl = (vk >> 4) & 1, pair = (vk >> 3) & 1, qc = (vk >> 1) & 3, elem = vk & 1;
    return (vk & ~31) + 8 * qc + kfl * 4 + pair * 2 + elem;
}
__device__ __forceinline__ int ak_to_vk(int ak) {
    int qc = (ak >> 3) & 3, j = ak & 7;
    return (ak & ~31) + (j >> 2) * 16 + ((j >> 1) & 1) * 8 + qc * 2 + (j & 1);
}

__global__ void __launch_bounds__(NTHR, 1) lstm_mma_kernel(
    const float* __restrict__ z,     const float* __restrict__ Wz,
    const float* __restrict__ bz,    const float* __restrict__ token,
    const float* __restrict__ Wi,    const float* __restrict__ Wh,
    const float* __restrict__ bh,    const float* __restrict__ Wout,
    const float* __restrict__ bout,  float* __restrict__ out)
{
    extern __shared__ char smem[];
    const uint32_t sb = smem_u32(smem);

    const int tid  = threadIdx.x;
    const int lane = tid & 31;
    const int w    = tid >> 5;            // warp 0..7 (m-tile)
    const int mh   = blockIdx.x & 1;      // batch half (independent sync domain)
    const int jg   = blockIdx.x >> 1;     // unit group 0..63 (8 units)
    const int m0   = mh * 128;
    const int j0   = jg * 8;

    const int qr   = lane >> 2;
    const int qc   = lane & 3;
    const int row0 = w * 16 + qr;
    const int u0   = qc * 2;

    const uint32_t bgLane = sb + BG_OFF + (uint32_t)(lane & 15) * BG_PITCH
                          + (uint32_t)(lane >> 4) * 16u;
    const uint32_t boLane = sb + BO_OFF + (uint32_t)(lane & 15) * BO_PITCH;

    float* sxg = (float*)(smem + XG_OFF);
    volatile unsigned* myCnt = &g_cnt[mh * 32];

    // ---------------- one-time init ----------------
    for (int i = tid; i < 1024; i += NTHR) ((uint4*)(smem + BO_OFF))[i] = make_uint4(0, 0, 0, 0);

    // Wh slice -> fp16 smem, VIRTUAL k order
    for (int idx = tid; idx < 512 * 32; idx += NTHR) {
        int vk = idx >> 5, n = idx & 31;
        int ak = vk_to_ak(vk);
        float v = __ldg(&Wh[(size_t)ak * G4H + (n >> 3) * HH + j0 + (n & 7)]);
        *(__half*)(smem + BG_OFF + (uint32_t)vk * BG_PITCH + (uint32_t)n * 2u) = __float2half_rn(v);
    }
    if (tid < 32) {
        int col = (tid >> 3) * HH + j0 + (tid & 7);
        float s = bh[col];
        #pragma unroll 4
        for (int k = 0; k < KTOK; ++k)
            s = fmaf(token[k], __ldg(&Wi[(size_t)k * G4H + col]), s);
        sxg[tid] = s;
    }
    {   // h0 = relu(z @ Wz + bz): thread -> row tid>>1, 4 units
        const int r  = tid >> 1;
        const int ub = (tid & 1) * 4;
        float a[4];
        #pragma unroll
        for (int q = 0; q < 4; ++q) a[q] = bz[j0 + ub + q];
        const float* zr = z + (size_t)(m0 + r) * KTOK;
        #pragma unroll 4
        for (int k = 0; k < KTOK; ++k) {
            float zv = __ldg(zr + k);
            float4 w4 = __ldg((const float4*)&Wz[(size_t)k * HH + j0 + ub]);
            a[0] = fmaf(zv, w4.x, a[0]); a[1] = fmaf(zv, w4.y, a[1]);
            a[2] = fmaf(zv, w4.z, a[2]); a[3] = fmaf(zv, w4.w, a[3]);
        }
        __half2* hp = (__half2*)&g_h[0][(size_t)(m0 + r) * HH + j0 + ub];
        hp[0] = __floats2half2_rn(fmaxf(a[0], 0.f), fmaxf(a[1], 0.f));
        hp[1] = __floats2half2_rn(fmaxf(a[2], 0.f), fmaxf(a[3], 0.f));
    }

    // initial counter barrier (ep = 1)
    unsigned ep = 1;
    __syncthreads();
    if (tid == 0) {
        __threadfence();
        asm volatile("red.global.add.u32 [%0], %1;" :: "l"((unsigned*)myCnt), "r"(1u) : "memory");
        while (*myCnt < ep * 64u) {}
        __threadfence();
    }
    __syncthreads();
    ++ep;

    float c4[4] = {0.f, 0.f, 0.f, 0.f};
    float2 wo0, wo1;

    // ---------------- sequential loop ----------------
    #pragma unroll 1
    for (int t = 0; t <= TT; ++t) {
        const __half* hsrc = g_h[t & 1];
        const int te = t - 1;

        const __half* aRow0 = hsrc + (size_t)(m0 + row0) * HH + 8 * qc;
        const __half* aRow8 = aRow0 + 8 * HH;
        const uint32_t boSel = boLane + (uint32_t)(t & 1) * BO_BUF;

        // A-fragment pipeline: 16 blocks of 32 k; 6-deep LDG.128 ring
        uint4 ra[6], rb[6];
        #pragma unroll
        for (int p = 0; p < 6; ++p) {
            ra[p] = __ldcg((const uint4*)(aRow0 + p * 32));
            rb[p] = __ldcg((const uint4*)(aRow8 + p * 32));
        }

        // prefetch Wout_t for next iteration (overlaps mainloop)
        if (t < TT) {
            const float* Wo = Wout + (size_t)t * HH * DD + jg * 2;
            wo0 = __ldcg((const float2*)(Wo + (size_t)(tid * 2) * DD));
            wo1 = __ldcg((const float2*)(Wo + (size_t)(tid * 2 + 1) * DD));
        }

        float acc[5][4];
        #pragma unroll
        for (int n = 0; n < 5; ++n)
            #pragma unroll
            for (int e = 0; e < 4; ++e) acc[n][e] = 0.f;

        // B-fragment register double buffer: preload ks = 0
        uint32_t bf[2][10];
        ldsm_x4t(&bf[0][0], bgLane);
        ldsm_x4t(&bf[0][4], bgLane + 32u);
        ldsm_x2t(&bf[0][8], boSel);

        #pragma unroll
        for (int b = 0; b < 16; ++b) {
            const int slot = b % 6;
            const uint4 va = ra[slot], vb = rb[slot];
            if (b + 6 < 16) {
                ra[slot] = __ldcg((const uint4*)(aRow0 + (b + 6) * 32));
                rb[slot] = __ldcg((const uint4*)(aRow8 + (b + 6) * 32));
            }
            #pragma unroll
            for (int kfl = 0; kfl < 2; ++kfl) {
                const int ks = b * 2 + kfl;
                const int cur = ks & 1;
                if (ks + 1 < 32) {   // prefetch next kfl's B fragments (hide ldsm latency)
                    const uint32_t nk = (uint32_t)((ks + 1) * 16);
                    ldsm_x4t(&bf[cur ^ 1][0], bgLane + nk * BG_PITCH);
                    ldsm_x4t(&bf[cur ^ 1][4], bgLane + nk * BG_PITCH + 32u);
                    ldsm_x2t(&bf[cur ^ 1][8], boSel + nk * BO_PITCH);
                }
                const uint32_t a0 = kfl ? va.z : va.x;
                const uint32_t a1 = kfl ? vb.z : vb.x;
                const uint32_t a2 = kfl ? va.w : va.y;
                const uint32_t a3 = kfl ? vb.w : vb.y;
                mma16816(acc[0], a0, a1, a2, a3, &bf[cur][0]);
                mma16816(acc[1], a0, a1, a2, a3, &bf[cur][2]);
                mma16816(acc[2], a0, a1, a2, a3, &bf[cur][4]);
                mma16816(acc[3], a0, a1, a2, a3, &bf[cur][6]);
                mma16816(acc[4], a0, a1, a2, a3, &bf[cur][8]);
            }
        }

        // ---- critical path: cell update + h store ----
        if (t < TT) {
            __half* hdst = &g_h[(t + 1) & 1][0];
            float hv[4];
            #pragma unroll
            for (int e = 0; e < 4; ++e) {
                const int u = u0 + (e & 1);
                float gi = sigm (acc[0][e] + sxg[u]);
                float gf = sigm (acc[1][e] + sxg[8 + u]);
                float gg = tanha(acc[2][e] + sxg[16 + u]);
                float go = sigm (acc[3][e] + sxg[24 + u]);
                float cv = gf * c4[e] + gi * gg;
                c4[e] = cv;
                hv[e] = go * tanha(cv);
            }
            __half2 h01 = __floats2half2_rn(hv[0], hv[1]);
            __half2 h23 = __floats2half2_rn(hv[2], hv[3]);
            __stcg((__half2*)&hdst[(size_t)(m0 + row0) * HH + j0 + u0], h01);
            __stcg((__half2*)&hdst[(size_t)(m0 + row0 + 8) * HH + j0 + u0], h23);
        }

        // ---- barrier arrive ----
        __syncthreads();
        if (t < TT && tid == 0) {
            __threadfence();
            asm volatile("red.global.add.u32 [%0], %1;" :: "l"((unsigned*)myCnt), "r"(1u) : "memory");
        }

        // ---- shadow work: out store + next-step BO staging (alternate buffer) ----
        if (t >= 1 && qc == 0) {
            const float2 bo = *(const float2*)&bout[te * DD + jg * 2];
            float2 o0 = make_float2(acc[4][0] + bo.x, acc[4][1] + bo.y);
            float2 o1 = make_float2(acc[4][2] + bo.x, acc[4][3] + bo.y);
            *(float2*)&out[(size_t)(m0 + row0) * TT * DD + (size_t)te * DD + jg * 2] = o0;
            *(float2*)&out[(size_t)(m0 + row0 + 8) * TT * DD + (size_t)te * DD + jg * 2] = o1;
        }
        if (t < TT) {
            const uint32_t boNext = BO_OFF + (uint32_t)((t + 1) & 1) * BO_BUF;
            __half2 p0 = __floats2half2_rn(wo0.x, wo0.y);
            __half2 p1 = __floats2half2_rn(wo1.x, wo1.y);
            *(uint32_t*)(smem + boNext + (uint32_t)ak_to_vk(tid * 2) * BO_PITCH)     = *(uint32_t*)&p0;
            *(uint32_t*)(smem + boNext + (uint32_t)ak_to_vk(tid * 2 + 1) * BO_PITCH) = *(uint32_t*)&p1;
        }

        // ---- barrier wait ----
        if (t < TT) {
            if (tid == 0) {
                while (*myCnt < ep * 64u) {}
                __threadfence();
            }
            __syncthreads();
            ++ep;
        }
    }
}

extern "C" void kernel_launch(void* const* d_in, const int* in_sizes, int n_in,
                              void* d_out, int out_size) {
    const float* z     = (const float*)d_in[0];
    const float* Wz    = (const float*)d_in[1];
    const float* bz    = (const float*)d_in[2];
    const float* token = (const float*)d_in[3];
    const float* Wi    = (const float*)d_in[4];
    const float* Wh    = (const float*)d_in[5];
    const float* bh    = (const float*)d_in[6];
    const float* Wout  = (const float*)d_in[7];
    const float* bout  = (const float*)d_in[8];
    float* out = (float*)d_out;

    cudaFuncSetAttribute(lstm_mma_kernel, cudaFuncAttributeMaxDynamicSharedMemorySize, SMEM_BYTES);
    reset_kernel<<<1, 64>>>();
    lstm_mma_kernel<<<NCTA, NTHR, SMEM_BYTES>>>(z, Wz, bz, token, Wi, Wh, bh, Wout, bout, out);
}